// round 1
// baseline (speedup 1.0000x reference)
#include <cuda_runtime.h>
#include <math.h>

#define C_DIM   1024
#define H_NUM   16
#define DH      64
#define FF_DIM  4096
#define B_NUM   2
#define T_LEN   2048
#define M_TOK   4096   // B*T

// ---------------- scratch (device globals; no allocation allowed) ----------
__device__ float g_h  [M_TOK * C_DIM];        // rmsnorm output (reused for h2)
__device__ float g_qkv[M_TOK * 3 * C_DIM];
__device__ float g_q  [M_TOK * C_DIM];        // [B,H,T,dh]
__device__ float g_k  [M_TOK * C_DIM];
__device__ float g_v  [M_TOK * C_DIM];
__device__ float g_o  [M_TOK * C_DIM];        // attention out, [B,T,H*dh]
__device__ float g_x1 [M_TOK * C_DIM];        // residual after attention
__device__ float g_ff [M_TOK * FF_DIM];       // a, then silu(a)*b

// ---------------- RMSNorm: one block per row (1024 elems, 256 thr) ---------
__global__ void rmsnorm_kernel(const float* __restrict__ x,
                               const float* __restrict__ g,
                               float* __restrict__ y) {
    int row = blockIdx.x;
    int tid = threadIdx.x;
    const float4* xr = (const float4*)(x + (size_t)row * C_DIM);
    const float4* gr = (const float4*)g;
    float4*       yr = (float4*)(y + (size_t)row * C_DIM);

    float4 xv = xr[tid];
    float ss = xv.x*xv.x + xv.y*xv.y + xv.z*xv.z + xv.w*xv.w;
    #pragma unroll
    for (int off = 16; off > 0; off >>= 1)
        ss += __shfl_xor_sync(0xffffffffu, ss, off);
    __shared__ float red[8];
    if ((tid & 31) == 0) red[tid >> 5] = ss;
    __syncthreads();
    float tot = 0.f;
    #pragma unroll
    for (int i = 0; i < 8; i++) tot += red[i];
    float inv = rsqrtf(tot * (1.0f / C_DIM) + 1e-5f);

    float4 gv = gr[tid];
    float4 o;
    o.x = xv.x * gv.x * inv;
    o.y = xv.y * gv.y * inv;
    o.z = xv.z * gv.z * inv;
    o.w = xv.w * gv.w * inv;
    yr[tid] = o;
}

// ---------------- SGEMM: C[M,N] = A[M,K] @ W[N,K]^T  (128x128x8, 8x8/thr) --
// MODE 0: C = A W^T
// MODE 1: C = X + A W^T                  (residual)
// MODE 2: C = silu(X) * (A W^T)          (X may alias C; elementwise-safe)
template <int MODE>
__global__ __launch_bounds__(256, 2)
void sgemm_kernel(const float* __restrict__ A, const float* __restrict__ W,
                  const float* X, float* Cout, int M, int N, int K) {
    __shared__ float As[8][132];
    __shared__ float Bs[8][132];

    int tid = threadIdx.x;                 // 256 threads
    int bm  = blockIdx.y * 128;
    int bn  = blockIdx.x * 128;
    int tx  = tid & 15;
    int ty  = tid >> 4;
    int row0 = ty * 8;
    int col0 = tx * 8;

    // global tile load mapping: 128 rows x 8 cols, one float4 per thread
    int lr = tid >> 1;
    int lc = (tid & 1) * 4;
    const float* Aptr = A + (size_t)(bm + lr) * K + lc;
    const float* Wptr = W + (size_t)(bn + lr) * K + lc;

    float acc[8][8];
    #pragma unroll
    for (int i = 0; i < 8; i++)
        #pragma unroll
        for (int j = 0; j < 8; j++) acc[i][j] = 0.f;

    for (int k0 = 0; k0 < K; k0 += 8) {
        float4 av = *(const float4*)(Aptr + k0);
        float4 wv = *(const float4*)(Wptr + k0);
        As[lc+0][lr] = av.x; As[lc+1][lr] = av.y;
        As[lc+2][lr] = av.z; As[lc+3][lr] = av.w;
        Bs[lc+0][lr] = wv.x; Bs[lc+1][lr] = wv.y;
        Bs[lc+2][lr] = wv.z; Bs[lc+3][lr] = wv.w;
        __syncthreads();

        #pragma unroll
        for (int kk = 0; kk < 8; kk++) {
            float a[8], b[8];
            *(float4*)&a[0] = *(const float4*)&As[kk][row0];
            *(float4*)&a[4] = *(const float4*)&As[kk][row0 + 4];
            *(float4*)&b[0] = *(const float4*)&Bs[kk][col0];
            *(float4*)&b[4] = *(const float4*)&Bs[kk][col0 + 4];
            #pragma unroll
            for (int i = 0; i < 8; i++)
                #pragma unroll
                for (int j = 0; j < 8; j++)
                    acc[i][j] = fmaf(a[i], b[j], acc[i][j]);
        }
        __syncthreads();
    }

    int cbase = bn + col0;
    #pragma unroll
    for (int i = 0; i < 8; i++) {
        int row = bm + row0 + i;
        float*       crow = Cout + (size_t)row * N + cbase;
        const float* xrow = (MODE != 0) ? (X + (size_t)row * N + cbase) : nullptr;
        #pragma unroll
        for (int j4 = 0; j4 < 8; j4 += 4) {
            float4 v;
            v.x = acc[i][j4+0]; v.y = acc[i][j4+1];
            v.z = acc[i][j4+2]; v.w = acc[i][j4+3];
            if (MODE == 1) {
                float4 xv = *(const float4*)(xrow + j4);
                v.x += xv.x; v.y += xv.y; v.z += xv.z; v.w += xv.w;
            }
            if (MODE == 2) {
                float4 xv = *(const float4*)(xrow + j4);
                v.x *= xv.x / (1.f + expf(-xv.x));
                v.y *= xv.y / (1.f + expf(-xv.y));
                v.z *= xv.z / (1.f + expf(-xv.z));
                v.w *= xv.w / (1.f + expf(-xv.w));
            }
            *(float4*)(crow + j4) = v;
        }
    }
}

// ---------------- RoPE + split qkv -> q,k,v in [B,H,T,dh] -------------------
// one thread per (token, head, pair)
__global__ void rope_split_kernel(const float* __restrict__ qkv,
                                  float* __restrict__ q,
                                  float* __restrict__ k,
                                  float* __restrict__ v) {
    int idx = blockIdx.x * blockDim.x + threadIdx.x;   // < M_TOK*16*32
    int i = idx & 31;          // pair index 0..31
    int h = (idx >> 5) & 15;   // head
    int m = idx >> 9;          // token row 0..4095
    int b = m >> 11;
    int t = m & 2047;

    const float* base = qkv + (size_t)m * (3 * C_DIM) + h * DH + 2 * i;
    float q1 = base[0],    q2 = base[1];
    float k1 = base[C_DIM], k2 = base[C_DIM + 1];
    float v1 = base[2*C_DIM], v2 = base[2*C_DIM + 1];

    // inv_freq = exp(-(2i)/64 * ln(10000))
    float freq = expf(-(2.0f * (float)i) * (1.0f / 64.0f) * 9.210340371976184f);
    float th = (float)t * freq;
    float s, c;
    sincosf(th, &s, &c);

    size_t o = ((size_t)(b * H_NUM + h) * T_LEN + t) * DH + 2 * i;
    q[o]   = q1 * c - q2 * s;
    q[o+1] = q1 * s + q2 * c;
    k[o]   = k1 * c - k2 * s;
    k[o+1] = k1 * s + k2 * c;
    v[o]   = v1;
    v[o+1] = v2;
}

// ---------------- causal flash attention -----------------------------------
// grid: (T/64, B*H); block 128 threads; 2 threads per query row (32 dims each)
__global__ void attn_kernel(const float* __restrict__ Q,
                            const float* __restrict__ Kg,
                            const float* __restrict__ Vg,
                            float* __restrict__ O) {
    __shared__ float Ks[64][64];
    __shared__ float Vs[64][64];

    int bh   = blockIdx.y;
    int b    = bh >> 4;
    int head = bh & 15;
    int q0   = blockIdx.x * 64;
    int tid  = threadIdx.x;
    int r    = q0 + (tid >> 1);
    int half = tid & 1;

    const float* qptr = Q + ((size_t)bh * T_LEN + r) * DH + half * 32;
    float qr[32];
    #pragma unroll
    for (int d = 0; d < 32; d++) qr[d] = qptr[d];

    float mrun = -1e30f, lrun = 0.f;
    float acc[32];
    #pragma unroll
    for (int d = 0; d < 32; d++) acc[d] = 0.f;

    int ntiles = q0 / 64 + 1;
    for (int kt = 0; kt < ntiles; kt++) {
        int ks = kt * 64;
        const float* kbase = Kg + ((size_t)bh * T_LEN + ks) * DH;
        const float* vbase = Vg + ((size_t)bh * T_LEN + ks) * DH;
        for (int li = tid; li < 64 * 16; li += 128) {
            int rr = li >> 4;
            int c4 = (li & 15) * 4;
            *(float4*)&Ks[rr][c4] = *(const float4*)(kbase + rr * DH + c4);
            *(float4*)&Vs[rr][c4] = *(const float4*)(vbase + rr * DH + c4);
        }
        __syncthreads();

        #pragma unroll 1
        for (int sc = 0; sc < 4; sc++) {
            int j0 = sc * 16;
            if (ks + j0 <= r) {
                float s[16];
                float tmax = -1e30f;
                #pragma unroll
                for (int j = 0; j < 16; j++) {
                    const float4* kr4 = (const float4*)&Ks[j0 + j][half * 32];
                    float p = 0.f;
                    #pragma unroll
                    for (int d4 = 0; d4 < 8; d4++) {
                        float4 kv = kr4[d4];
                        p = fmaf(qr[4*d4+0], kv.x, p);
                        p = fmaf(qr[4*d4+1], kv.y, p);
                        p = fmaf(qr[4*d4+2], kv.z, p);
                        p = fmaf(qr[4*d4+3], kv.w, p);
                    }
                    p += __shfl_xor_sync(0xffffffffu, p, 1);
                    p *= 0.125f;                       // 1/sqrt(64)
                    if (ks + j0 + j > r) p = -1e30f;   // causal mask
                    s[j] = p;
                    tmax = fmaxf(tmax, p);
                }
                float mnew = fmaxf(mrun, tmax);
                float corr = expf(mrun - mnew);
                lrun *= corr;
                #pragma unroll
                for (int d = 0; d < 32; d++) acc[d] *= corr;
                #pragma unroll
                for (int j = 0; j < 16; j++) {
                    float p = expf(s[j] - mnew);
                    lrun += p;
                    const float4* vr4 = (const float4*)&Vs[j0 + j][half * 32];
                    #pragma unroll
                    for (int d4 = 0; d4 < 8; d4++) {
                        float4 vv = vr4[d4];
                        acc[4*d4+0] = fmaf(p, vv.x, acc[4*d4+0]);
                        acc[4*d4+1] = fmaf(p, vv.y, acc[4*d4+1]);
                        acc[4*d4+2] = fmaf(p, vv.z, acc[4*d4+2]);
                        acc[4*d4+3] = fmaf(p, vv.w, acc[4*d4+3]);
                    }
                }
                mrun = mnew;
            }
        }
        __syncthreads();
    }

    float inv = 1.0f / lrun;
    float* optr = O + ((size_t)(b * T_LEN + r) * C_DIM) + head * DH + half * 32;
    #pragma unroll
    for (int d = 0; d < 32; d++) optr[d] = acc[d] * inv;
}

// ---------------- launch ----------------------------------------------------
extern "C" void kernel_launch(void* const* d_in, const int* in_sizes, int n_in,
                              void* d_out, int out_size) {
    const float* x      = (const float*)d_in[0];
    const float* w_qkv  = (const float*)d_in[1];
    const float* w_proj = (const float*)d_in[2];
    const float* g1     = (const float*)d_in[3];
    const float* g2     = (const float*)d_in[4];
    const float* w1     = (const float*)d_in[5];
    const float* w2     = (const float*)d_in[6];
    const float* w3     = (const float*)d_in[7];
    float* out = (float*)d_out;

    float *p_h, *p_qkv, *p_q, *p_k, *p_v, *p_o, *p_x1, *p_ff;
    cudaGetSymbolAddress((void**)&p_h,   g_h);
    cudaGetSymbolAddress((void**)&p_qkv, g_qkv);
    cudaGetSymbolAddress((void**)&p_q,   g_q);
    cudaGetSymbolAddress((void**)&p_k,   g_k);
    cudaGetSymbolAddress((void**)&p_v,   g_v);
    cudaGetSymbolAddress((void**)&p_o,   g_o);
    cudaGetSymbolAddress((void**)&p_x1,  g_x1);
    cudaGetSymbolAddress((void**)&p_ff,  g_ff);

    // 1) h = rmsnorm(x, g1)
    rmsnorm_kernel<<<M_TOK, 256>>>(x, g1, p_h);
    // 2) qkv = h @ w_qkv^T
    sgemm_kernel<0><<<dim3(3 * C_DIM / 128, M_TOK / 128), 256>>>(
        p_h, w_qkv, nullptr, p_qkv, M_TOK, 3 * C_DIM, C_DIM);
    // 3) rope + split into [B,H,T,dh]
    rope_split_kernel<<<(M_TOK * H_NUM * 32) / 256, 256>>>(p_qkv, p_q, p_k, p_v);
    // 4) causal attention -> o in [B,T,C]
    attn_kernel<<<dim3(T_LEN / 64, B_NUM * H_NUM), 128>>>(p_q, p_k, p_v, p_o);
    // 5) x1 = x + o @ w_proj^T
    sgemm_kernel<1><<<dim3(C_DIM / 128, M_TOK / 128), 256>>>(
        p_o, w_proj, x, p_x1, M_TOK, C_DIM, C_DIM);
    // 6) h2 = rmsnorm(x1, g2)  (reuse g_h)
    rmsnorm_kernel<<<M_TOK, 256>>>(p_x1, g2, p_h);
    // 7) a = h2 @ w1^T
    sgemm_kernel<0><<<dim3(FF_DIM / 128, M_TOK / 128), 256>>>(
        p_h, w1, nullptr, p_ff, M_TOK, FF_DIM, C_DIM);
    // 8) ff = silu(a) * (h2 @ w3^T)   (reads a from p_ff, writes in place)
    sgemm_kernel<2><<<dim3(FF_DIM / 128, M_TOK / 128), 256>>>(
        p_h, w3, p_ff, p_ff, M_TOK, FF_DIM, C_DIM);
    // 9) out = x1 + ff @ w2^T
    sgemm_kernel<1><<<dim3(C_DIM / 128, M_TOK / 128), 256>>>(
        p_ff, w2, p_x1, out, M_TOK, C_DIM, FF_DIM);
}

// round 2
// speedup vs baseline: 1.6245x; 1.6245x over previous
#include <cuda_runtime.h>
#include <math.h>
#include <stdint.h>

#define C_DIM   1024
#define H_NUM   16
#define DH      64
#define FF_DIM  4096
#define B_NUM   2
#define T_LEN   2048
#define M_TOK   4096   // B*T

// ---------------- scratch (device globals; no allocation allowed) ----------
__device__ float g_h  [M_TOK * C_DIM];        // rmsnorm output (reused for h2)
__device__ float g_qkv[M_TOK * 3 * C_DIM];
__device__ float g_q  [M_TOK * C_DIM];        // [B,H,T,dh]
__device__ float g_k  [M_TOK * C_DIM];
__device__ float g_v  [M_TOK * C_DIM];
__device__ float g_o  [M_TOK * C_DIM];        // attention out, [B,T,H*dh]
__device__ float g_x1 [M_TOK * C_DIM];        // residual after attention
__device__ float g_ff [M_TOK * FF_DIM];       // a, then silu(a)*b

// ---------------- helpers ----------------------------------------------------
__device__ __forceinline__ uint32_t f2tf32(float x) {
    uint32_t r;
    asm("cvt.rna.tf32.f32 %0, %1;" : "=r"(r) : "f"(x));
    return r;
}

__device__ __forceinline__ void mma_tf32(float c[4],
                                         uint32_t a0, uint32_t a1, uint32_t a2, uint32_t a3,
                                         uint32_t b0, uint32_t b1) {
    asm volatile(
        "mma.sync.aligned.m16n8k8.row.col.f32.tf32.tf32.f32 "
        "{%0,%1,%2,%3}, {%4,%5,%6,%7}, {%8,%9}, {%0,%1,%2,%3};\n"
        : "+f"(c[0]), "+f"(c[1]), "+f"(c[2]), "+f"(c[3])
        : "r"(a0), "r"(a1), "r"(a2), "r"(a3), "r"(b0), "r"(b1));
}

// ---------------- RMSNorm: one block per row (1024 elems, 256 thr) ---------
__global__ void rmsnorm_kernel(const float* __restrict__ x,
                               const float* __restrict__ g,
                               float* __restrict__ y) {
    int row = blockIdx.x;
    int tid = threadIdx.x;
    const float4* xr = (const float4*)(x + (size_t)row * C_DIM);
    const float4* gr = (const float4*)g;
    float4*       yr = (float4*)(y + (size_t)row * C_DIM);

    float4 xv = xr[tid];
    float ss = xv.x*xv.x + xv.y*xv.y + xv.z*xv.z + xv.w*xv.w;
    #pragma unroll
    for (int off = 16; off > 0; off >>= 1)
        ss += __shfl_xor_sync(0xffffffffu, ss, off);
    __shared__ float red[8];
    if ((tid & 31) == 0) red[tid >> 5] = ss;
    __syncthreads();
    float tot = 0.f;
    #pragma unroll
    for (int i = 0; i < 8; i++) tot += red[i];
    float inv = rsqrtf(tot * (1.0f / C_DIM) + 1e-5f);

    float4 gv = gr[tid];
    float4 o;
    o.x = xv.x * gv.x * inv;
    o.y = xv.y * gv.y * inv;
    o.z = xv.z * gv.z * inv;
    o.w = xv.w * gv.w * inv;
    yr[tid] = o;
}

// ---------------- tf32 tensor-core GEMM: C[M,N] = A[M,K] @ W[N,K]^T ---------
// Block 128x128, K-step 8. 8 warps in 4(m) x 2(n) grid; warp tile 32m x 64n.
// Per k-step each warp issues 2x8 = 16 mma.m16n8k8 ops.
// MODE 0: C = A W^T
// MODE 1: C = X + A W^T                  (residual)
// MODE 2: C = silu(X) * (A W^T)          (X may alias C; elementwise-safe)
template <int MODE>
__global__ __launch_bounds__(256, 2)
void tgemm_kernel(const float* __restrict__ A, const float* __restrict__ W,
                  const float* X, float* Cout, int M, int N, int K) {
    __shared__ float As[8][136];   // [k][m], stride 136 -> conflict-free frags
    __shared__ float Bs[8][136];   // [k][n]

    int tid  = threadIdx.x;
    int bm   = blockIdx.y * 128;
    int bn   = blockIdx.x * 128;
    int warp = tid >> 5;
    int lane = tid & 31;
    int wm   = (warp >> 1) * 32;   // warp m-offset (0,32,64,96)
    int wn   = (warp & 1) * 64;    // warp n-offset (0,64)
    int g    = lane >> 2;          // 0..7
    int t    = lane & 3;           // 0..3

    // global tile load mapping: 128 rows x 8 cols, one float4 per thread
    int lr = tid >> 1;
    int lc = (tid & 1) * 4;
    const float* Aptr = A + (size_t)(bm + lr) * K + lc;
    const float* Wptr = W + (size_t)(bn + lr) * K + lc;

    float c[2][8][4];
    #pragma unroll
    for (int mt = 0; mt < 2; mt++)
        #pragma unroll
        for (int nt = 0; nt < 8; nt++)
            #pragma unroll
            for (int i = 0; i < 4; i++) c[mt][nt][i] = 0.f;

    for (int k0 = 0; k0 < K; k0 += 8) {
        float4 av = *(const float4*)(Aptr + k0);
        float4 wv = *(const float4*)(Wptr + k0);
        // round to tf32 once at smem-store time
        As[lc+0][lr] = __uint_as_float(f2tf32(av.x));
        As[lc+1][lr] = __uint_as_float(f2tf32(av.y));
        As[lc+2][lr] = __uint_as_float(f2tf32(av.z));
        As[lc+3][lr] = __uint_as_float(f2tf32(av.w));
        Bs[lc+0][lr] = __uint_as_float(f2tf32(wv.x));
        Bs[lc+1][lr] = __uint_as_float(f2tf32(wv.y));
        Bs[lc+2][lr] = __uint_as_float(f2tf32(wv.z));
        Bs[lc+3][lr] = __uint_as_float(f2tf32(wv.w));
        __syncthreads();

        // fragment loads (A[m][k] = As[k][m]; B[n][k] = Bs[k][n])
        uint32_t aR[2][4];
        #pragma unroll
        for (int mt = 0; mt < 2; mt++) {
            int m0 = wm + mt * 16;
            aR[mt][0] = __float_as_uint(As[t    ][m0 + g    ]);
            aR[mt][1] = __float_as_uint(As[t    ][m0 + 8 + g]);
            aR[mt][2] = __float_as_uint(As[t + 4][m0 + g    ]);
            aR[mt][3] = __float_as_uint(As[t + 4][m0 + 8 + g]);
        }
        uint32_t bR[8][2];
        #pragma unroll
        for (int nt = 0; nt < 8; nt++) {
            int n0 = wn + nt * 8;
            bR[nt][0] = __float_as_uint(Bs[t    ][n0 + g]);
            bR[nt][1] = __float_as_uint(Bs[t + 4][n0 + g]);
        }
        #pragma unroll
        for (int mt = 0; mt < 2; mt++)
            #pragma unroll
            for (int nt = 0; nt < 8; nt++)
                mma_tf32(c[mt][nt], aR[mt][0], aR[mt][1], aR[mt][2], aR[mt][3],
                         bR[nt][0], bR[nt][1]);
        __syncthreads();
    }

    // epilogue: c layout -> row = bm+wm+mt*16+half*8+g, col = bn+wn+nt*8+2t
    #pragma unroll
    for (int mt = 0; mt < 2; mt++) {
        #pragma unroll
        for (int half = 0; half < 2; half++) {
            int row = bm + wm + mt * 16 + half * 8 + g;
            float*       crow = Cout + (size_t)row * N;
            const float* xrow = (MODE != 0) ? (X + (size_t)row * N) : nullptr;
            #pragma unroll
            for (int nt = 0; nt < 8; nt++) {
                int col = bn + wn + nt * 8 + 2 * t;
                float2 v;
                v.x = c[mt][nt][half * 2 + 0];
                v.y = c[mt][nt][half * 2 + 1];
                if (MODE == 1) {
                    float2 xv = *(const float2*)(xrow + col);
                    v.x += xv.x; v.y += xv.y;
                }
                if (MODE == 2) {
                    float2 xv = *(const float2*)(xrow + col);
                    v.x *= xv.x / (1.f + expf(-xv.x));
                    v.y *= xv.y / (1.f + expf(-xv.y));
                }
                *(float2*)(crow + col) = v;
            }
        }
    }
}

// ---------------- RoPE + split qkv -> q,k,v in [B,H,T,dh] -------------------
__global__ void rope_split_kernel(const float* __restrict__ qkv,
                                  float* __restrict__ q,
                                  float* __restrict__ k,
                                  float* __restrict__ v) {
    int idx = blockIdx.x * blockDim.x + threadIdx.x;   // < M_TOK*16*32
    int i = idx & 31;          // pair index 0..31
    int h = (idx >> 5) & 15;   // head
    int m = idx >> 9;          // token row 0..4095
    int b = m >> 11;
    int t = m & 2047;

    const float* base = qkv + (size_t)m * (3 * C_DIM) + h * DH + 2 * i;
    float q1 = base[0],       q2 = base[1];
    float k1 = base[C_DIM],   k2 = base[C_DIM + 1];
    float v1 = base[2*C_DIM], v2 = base[2*C_DIM + 1];

    float freq = expf(-(2.0f * (float)i) * (1.0f / 64.0f) * 9.210340371976184f);
    float th = (float)t * freq;
    float s, c;
    sincosf(th, &s, &c);

    size_t o = ((size_t)(b * H_NUM + h) * T_LEN + t) * DH + 2 * i;
    q[o]   = q1 * c - q2 * s;
    q[o+1] = q1 * s + q2 * c;
    k[o]   = k1 * c - k2 * s;
    k[o+1] = k1 * s + k2 * c;
    v[o]   = v1;
    v[o+1] = v2;
}

// ---------------- causal flash attention -----------------------------------
__global__ void attn_kernel(const float* __restrict__ Q,
                            const float* __restrict__ Kg,
                            const float* __restrict__ Vg,
                            float* __restrict__ O) {
    __shared__ float Ks[64][64];
    __shared__ float Vs[64][64];

    int bh   = blockIdx.y;
    int b    = bh >> 4;
    int head = bh & 15;
    int q0   = blockIdx.x * 64;
    int tid  = threadIdx.x;
    int r    = q0 + (tid >> 1);
    int half = tid & 1;

    const float* qptr = Q + ((size_t)bh * T_LEN + r) * DH + half * 32;
    float qr[32];
    #pragma unroll
    for (int d = 0; d < 32; d++) qr[d] = qptr[d];

    float mrun = -1e30f, lrun = 0.f;
    float acc[32];
    #pragma unroll
    for (int d = 0; d < 32; d++) acc[d] = 0.f;

    int ntiles = q0 / 64 + 1;
    for (int kt = 0; kt < ntiles; kt++) {
        int ks = kt * 64;
        const float* kbase = Kg + ((size_t)bh * T_LEN + ks) * DH;
        const float* vbase = Vg + ((size_t)bh * T_LEN + ks) * DH;
        for (int li = tid; li < 64 * 16; li += 128) {
            int rr = li >> 4;
            int c4 = (li & 15) * 4;
            *(float4*)&Ks[rr][c4] = *(const float4*)(kbase + rr * DH + c4);
            *(float4*)&Vs[rr][c4] = *(const float4*)(vbase + rr * DH + c4);
        }
        __syncthreads();

        #pragma unroll 1
        for (int sc = 0; sc < 4; sc++) {
            int j0 = sc * 16;
            if (ks + j0 <= r) {
                float s[16];
                float tmax = -1e30f;
                #pragma unroll
                for (int j = 0; j < 16; j++) {
                    const float4* kr4 = (const float4*)&Ks[j0 + j][half * 32];
                    float p = 0.f;
                    #pragma unroll
                    for (int d4 = 0; d4 < 8; d4++) {
                        float4 kv = kr4[d4];
                        p = fmaf(qr[4*d4+0], kv.x, p);
                        p = fmaf(qr[4*d4+1], kv.y, p);
                        p = fmaf(qr[4*d4+2], kv.z, p);
                        p = fmaf(qr[4*d4+3], kv.w, p);
                    }
                    p += __shfl_xor_sync(0xffffffffu, p, 1);
                    p *= 0.125f;
                    if (ks + j0 + j > r) p = -1e30f;
                    s[j] = p;
                    tmax = fmaxf(tmax, p);
                }
                float mnew = fmaxf(mrun, tmax);
                float corr = expf(mrun - mnew);
                lrun *= corr;
                #pragma unroll
                for (int d = 0; d < 32; d++) acc[d] *= corr;
                #pragma unroll
                for (int j = 0; j < 16; j++) {
                    float p = expf(s[j] - mnew);
                    lrun += p;
                    const float4* vr4 = (const float4*)&Vs[j0 + j][half * 32];
                    #pragma unroll
                    for (int d4 = 0; d4 < 8; d4++) {
                        float4 vv = vr4[d4];
                        acc[4*d4+0] = fmaf(p, vv.x, acc[4*d4+0]);
                        acc[4*d4+1] = fmaf(p, vv.y, acc[4*d4+1]);
                        acc[4*d4+2] = fmaf(p, vv.z, acc[4*d4+2]);
                        acc[4*d4+3] = fmaf(p, vv.w, acc[4*d4+3]);
                    }
                }
                mrun = mnew;
            }
        }
        __syncthreads();
    }

    float inv = 1.0f / lrun;
    float* optr = O + ((size_t)(b * T_LEN + r) * C_DIM) + head * DH + half * 32;
    #pragma unroll
    for (int d = 0; d < 32; d++) optr[d] = acc[d] * inv;
}

// ---------------- launch ----------------------------------------------------
extern "C" void kernel_launch(void* const* d_in, const int* in_sizes, int n_in,
                              void* d_out, int out_size) {
    const float* x      = (const float*)d_in[0];
    const float* w_qkv  = (const float*)d_in[1];
    const float* w_proj = (const float*)d_in[2];
    const float* g1     = (const float*)d_in[3];
    const float* g2     = (const float*)d_in[4];
    const float* w1     = (const float*)d_in[5];
    const float* w2     = (const float*)d_in[6];
    const float* w3     = (const float*)d_in[7];
    float* out = (float*)d_out;

    float *p_h, *p_qkv, *p_q, *p_k, *p_v, *p_o, *p_x1, *p_ff;
    cudaGetSymbolAddress((void**)&p_h,   g_h);
    cudaGetSymbolAddress((void**)&p_qkv, g_qkv);
    cudaGetSymbolAddress((void**)&p_q,   g_q);
    cudaGetSymbolAddress((void**)&p_k,   g_k);
    cudaGetSymbolAddress((void**)&p_v,   g_v);
    cudaGetSymbolAddress((void**)&p_o,   g_o);
    cudaGetSymbolAddress((void**)&p_x1,  g_x1);
    cudaGetSymbolAddress((void**)&p_ff,  g_ff);

    // 1) h = rmsnorm(x, g1)
    rmsnorm_kernel<<<M_TOK, 256>>>(x, g1, p_h);
    // 2) qkv = h @ w_qkv^T
    tgemm_kernel<0><<<dim3(3 * C_DIM / 128, M_TOK / 128), 256>>>(
        p_h, w_qkv, nullptr, p_qkv, M_TOK, 3 * C_DIM, C_DIM);
    // 3) rope + split into [B,H,T,dh]
    rope_split_kernel<<<(M_TOK * H_NUM * 32) / 256, 256>>>(p_qkv, p_q, p_k, p_v);
    // 4) causal attention -> o in [B,T,C]
    attn_kernel<<<dim3(T_LEN / 64, B_NUM * H_NUM), 128>>>(p_q, p_k, p_v, p_o);
    // 5) x1 = x + o @ w_proj^T
    tgemm_kernel<1><<<dim3(C_DIM / 128, M_TOK / 128), 256>>>(
        p_o, w_proj, x, p_x1, M_TOK, C_DIM, C_DIM);
    // 6) h2 = rmsnorm(x1, g2)  (reuse g_h)
    rmsnorm_kernel<<<M_TOK, 256>>>(p_x1, g2, p_h);
    // 7) a = h2 @ w1^T
    tgemm_kernel<0><<<dim3(FF_DIM / 128, M_TOK / 128), 256>>>(
        p_h, w1, nullptr, p_ff, M_TOK, FF_DIM, C_DIM);
    // 8) ff = silu(a) * (h2 @ w3^T)
    tgemm_kernel<2><<<dim3(FF_DIM / 128, M_TOK / 128), 256>>>(
        p_h, w3, p_ff, p_ff, M_TOK, FF_DIM, C_DIM);
    // 9) out = x1 + ff @ w2^T
    tgemm_kernel<1><<<dim3(C_DIM / 128, M_TOK / 128), 256>>>(
        p_ff, w2, p_x1, out, M_TOK, C_DIM, FF_DIM);
}

// round 3
// speedup vs baseline: 1.8805x; 1.1576x over previous
#include <cuda_runtime.h>
#include <math.h>
#include <stdint.h>

#define C_DIM   1024
#define H_NUM   16
#define DH      64
#define FF_DIM  4096
#define B_NUM   2
#define T_LEN   2048
#define M_TOK   4096   // B*T

// ---------------- scratch (device globals; no allocation allowed) ----------
__device__ float g_h  [M_TOK * C_DIM];
__device__ float g_qkv[M_TOK * 3 * C_DIM];
__device__ float g_q  [M_TOK * C_DIM];        // [B,H,T,dh]
__device__ float g_k  [M_TOK * C_DIM];
__device__ float g_v  [M_TOK * C_DIM];
__device__ float g_o  [M_TOK * C_DIM];        // attention out, [B,T,H*dh]
__device__ float g_x1 [M_TOK * C_DIM];
__device__ float g_ff [M_TOK * FF_DIM];

// ---------------- helpers ----------------------------------------------------
__device__ __forceinline__ uint32_t f2tf32(float x) {
    uint32_t r;
    asm("cvt.rna.tf32.f32 %0, %1;" : "=r"(r) : "f"(x));
    return r;
}
__device__ __forceinline__ float4 tf32x4(float4 v) {
    v.x = __uint_as_float(f2tf32(v.x));
    v.y = __uint_as_float(f2tf32(v.y));
    v.z = __uint_as_float(f2tf32(v.z));
    v.w = __uint_as_float(f2tf32(v.w));
    return v;
}
__device__ __forceinline__ void mma_tf32(float c[4],
                                         uint32_t a0, uint32_t a1, uint32_t a2, uint32_t a3,
                                         uint32_t b0, uint32_t b1) {
    asm volatile(
        "mma.sync.aligned.m16n8k8.row.col.f32.tf32.tf32.f32 "
        "{%0,%1,%2,%3}, {%4,%5,%6,%7}, {%8,%9}, {%0,%1,%2,%3};\n"
        : "+f"(c[0]), "+f"(c[1]), "+f"(c[2]), "+f"(c[3])
        : "r"(a0), "r"(a1), "r"(a2), "r"(a3), "r"(b0), "r"(b1));
}
__device__ __forceinline__ void ldsm4(uint32_t& r0, uint32_t& r1,
                                      uint32_t& r2, uint32_t& r3, uint32_t addr) {
    asm volatile("ldmatrix.sync.aligned.m8n8.x4.shared.b16 {%0,%1,%2,%3}, [%4];"
                 : "=r"(r0), "=r"(r1), "=r"(r2), "=r"(r3) : "r"(addr));
}

// ---------------- RMSNorm ----------------------------------------------------
__global__ void rmsnorm_kernel(const float* __restrict__ x,
                               const float* __restrict__ g,
                               float* __restrict__ y) {
    int row = blockIdx.x;
    int tid = threadIdx.x;
    const float4* xr = (const float4*)(x + (size_t)row * C_DIM);
    const float4* gr = (const float4*)g;
    float4*       yr = (float4*)(y + (size_t)row * C_DIM);

    float4 xv = xr[tid];
    float ss = xv.x*xv.x + xv.y*xv.y + xv.z*xv.z + xv.w*xv.w;
    #pragma unroll
    for (int off = 16; off > 0; off >>= 1)
        ss += __shfl_xor_sync(0xffffffffu, ss, off);
    __shared__ float red[8];
    if ((tid & 31) == 0) red[tid >> 5] = ss;
    __syncthreads();
    float tot = 0.f;
    #pragma unroll
    for (int i = 0; i < 8; i++) tot += red[i];
    float inv = rsqrtf(tot * (1.0f / C_DIM) + 1e-5f);

    float4 gv = gr[tid];
    float4 o;
    o.x = xv.x * gv.x * inv;
    o.y = xv.y * gv.y * inv;
    o.z = xv.z * gv.z * inv;
    o.w = xv.w * gv.w * inv;
    yr[tid] = o;
}

// ---------------- tf32 tensor-core GEMM: C[M,N] = A[M,K] @ W[N,K]^T ---------
// Block 128x128, BK=16, double-buffered. 8 warps (4m x 2n), warp tile 32x64.
// Fragments via ldmatrix.x4; smem tiles [row][k8] with XOR swizzle.
template <int MODE>
__global__ __launch_bounds__(256, 2)
void tgemm_kernel(const float* __restrict__ A, const float* __restrict__ W,
                  const float* X, float* Cout, int M, int N, int K) {
    // [stage][q(k8-half)][row*8 + swizzled col]
    __shared__ float sA[2][2][128 * 8];
    __shared__ float sB[2][2][128 * 8];

    int tid  = threadIdx.x;
    int bm   = blockIdx.y * 128;
    int bn   = blockIdx.x * 128;
    int warp = tid >> 5;
    int lane = tid & 31;
    int wm   = (warp >> 1) * 32;
    int wn   = (warp & 1) * 64;

    // global load mapping: row = tid>>1, chunk c = tid&1 (k-offset 4c within k8)
    int lr = tid >> 1;
    int cc = tid & 1;
    const float* Aptr = A + (size_t)(bm + lr) * K + cc * 4;
    const float* Wptr = W + (size_t)(bn + lr) * K + cc * 4;
    int sstore = lr * 8 + ((cc ^ ((lr >> 2) & 1)) << 2);   // swizzled float index

    // ldmatrix per-thread byte offsets within one [128*8] q-tile
    int i   = lane & 7;
    int sub = lane >> 3;
    uint32_t aBase = (uint32_t)__cvta_generic_to_shared(&sA[0][0][0]);
    uint32_t bBase = (uint32_t)__cvta_generic_to_shared(&sB[0][0][0]);
    uint32_t offA[2], offB[4];
    #pragma unroll
    for (int mt = 0; mt < 2; mt++) {
        int row = wm + mt * 16 + (sub & 1) * 8 + i;
        int ch  = (sub >> 1) ^ ((row >> 2) & 1);
        offA[mt] = (uint32_t)(row * 8 + ch * 4) * 4u;
    }
    #pragma unroll
    for (int p = 0; p < 4; p++) {
        int row = wn + p * 16 + (sub >> 1) * 8 + i;
        int ch  = (sub & 1) ^ ((row >> 2) & 1);
        offB[p] = (uint32_t)(row * 8 + ch * 4) * 4u;
    }

    float acc[2][8][4];
    #pragma unroll
    for (int mt = 0; mt < 2; mt++)
        #pragma unroll
        for (int nt = 0; nt < 8; nt++)
            #pragma unroll
            for (int e = 0; e < 4; e++) acc[mt][nt][e] = 0.f;

    // prologue: fill stage 0 (k = 0..15)
    {
        float4 a0 = tf32x4(*(const float4*)(Aptr));
        float4 a1 = tf32x4(*(const float4*)(Aptr + 8));
        float4 b0 = tf32x4(*(const float4*)(Wptr));
        float4 b1 = tf32x4(*(const float4*)(Wptr + 8));
        *(float4*)&sA[0][0][sstore] = a0;
        *(float4*)&sA[0][1][sstore] = a1;
        *(float4*)&sB[0][0][sstore] = b0;
        *(float4*)&sB[0][1][sstore] = b1;
    }
    __syncthreads();

    int st = 0;
    for (int k0 = 0; k0 < K; k0 += 16) {
        bool more = (k0 + 16) < K;
        float4 na0, na1, nb0, nb1;
        if (more) {
            na0 = *(const float4*)(Aptr + k0 + 16);
            na1 = *(const float4*)(Aptr + k0 + 24);
            nb0 = *(const float4*)(Wptr + k0 + 16);
            nb1 = *(const float4*)(Wptr + k0 + 24);
        }

        #pragma unroll
        for (int q = 0; q < 2; q++) {
            uint32_t tile = (uint32_t)(st * 2 + q) * (128 * 8 * 4);
            uint32_t aR[2][4], bR[4][4];
            ldsm4(aR[0][0], aR[0][1], aR[0][2], aR[0][3], aBase + tile + offA[0]);
            ldsm4(aR[1][0], aR[1][1], aR[1][2], aR[1][3], aBase + tile + offA[1]);
            #pragma unroll
            for (int p = 0; p < 4; p++)
                ldsm4(bR[p][0], bR[p][1], bR[p][2], bR[p][3], bBase + tile + offB[p]);
            #pragma unroll
            for (int mt = 0; mt < 2; mt++)
                #pragma unroll
                for (int nt = 0; nt < 8; nt++) {
                    int p  = nt >> 1;
                    int e0 = (nt & 1) * 2;
                    mma_tf32(acc[mt][nt],
                             aR[mt][0], aR[mt][1], aR[mt][2], aR[mt][3],
                             bR[p][e0], bR[p][e0 + 1]);
                }
        }

        if (more) {
            *(float4*)&sA[st ^ 1][0][sstore] = tf32x4(na0);
            *(float4*)&sA[st ^ 1][1][sstore] = tf32x4(na1);
            *(float4*)&sB[st ^ 1][0][sstore] = tf32x4(nb0);
            *(float4*)&sB[st ^ 1][1][sstore] = tf32x4(nb1);
        }
        __syncthreads();
        st ^= 1;
    }

    // epilogue: row = bm+wm+mt*16+half*8+(lane>>2), col = bn+wn+nt*8+2*(lane&3)
    int g = lane >> 2;
    int t = lane & 3;
    #pragma unroll
    for (int mt = 0; mt < 2; mt++) {
        #pragma unroll
        for (int half = 0; half < 2; half++) {
            int row = bm + wm + mt * 16 + half * 8 + g;
            float*       crow = Cout + (size_t)row * N;
            const float* xrow = (MODE != 0) ? (X + (size_t)row * N) : nullptr;
            #pragma unroll
            for (int nt = 0; nt < 8; nt++) {
                int col = bn + wn + nt * 8 + 2 * t;
                float2 v;
                v.x = acc[mt][nt][half * 2 + 0];
                v.y = acc[mt][nt][half * 2 + 1];
                if (MODE == 1) {
                    float2 xv = *(const float2*)(xrow + col);
                    v.x += xv.x; v.y += xv.y;
                }
                if (MODE == 2) {
                    float2 xv = *(const float2*)(xrow + col);
                    v.x *= xv.x / (1.f + expf(-xv.x));
                    v.y *= xv.y / (1.f + expf(-xv.y));
                }
                *(float2*)(crow + col) = v;
            }
        }
    }
}

// ---------------- RoPE + split qkv -> q,k,v in [B,H,T,dh] -------------------
__global__ void rope_split_kernel(const float* __restrict__ qkv,
                                  float* __restrict__ q,
                                  float* __restrict__ k,
                                  float* __restrict__ v) {
    int idx = blockIdx.x * blockDim.x + threadIdx.x;
    int i = idx & 31;
    int h = (idx >> 5) & 15;
    int m = idx >> 9;
    int b = m >> 11;
    int t = m & 2047;

    const float* base = qkv + (size_t)m * (3 * C_DIM) + h * DH + 2 * i;
    float q1 = base[0],       q2 = base[1];
    float k1 = base[C_DIM],   k2 = base[C_DIM + 1];
    float v1 = base[2*C_DIM], v2 = base[2*C_DIM + 1];

    float freq = expf(-(2.0f * (float)i) * (1.0f / 64.0f) * 9.210340371976184f);
    float th = (float)t * freq;
    float s, c;
    sincosf(th, &s, &c);

    size_t o = ((size_t)(b * H_NUM + h) * T_LEN + t) * DH + 2 * i;
    q[o]   = q1 * c - q2 * s;
    q[o+1] = q1 * s + q2 * c;
    k[o]   = k1 * c - k2 * s;
    k[o+1] = k1 * s + k2 * c;
    v[o]   = v1;
    v[o+1] = v2;
}

// ---------------- causal flash attention -----------------------------------
__global__ void attn_kernel(const float* __restrict__ Q,
                            const float* __restrict__ Kg,
                            const float* __restrict__ Vg,
                            float* __restrict__ O) {
    __shared__ float Ks[64][64];
    __shared__ float Vs[64][64];

    int bh   = blockIdx.y;
    int b    = bh >> 4;
    int head = bh & 15;
    int q0   = blockIdx.x * 64;
    int tid  = threadIdx.x;
    int r    = q0 + (tid >> 1);
    int half = tid & 1;

    const float* qptr = Q + ((size_t)bh * T_LEN + r) * DH + half * 32;
    float qr[32];
    #pragma unroll
    for (int d = 0; d < 32; d++) qr[d] = qptr[d];

    float mrun = -1e30f, lrun = 0.f;
    float acc[32];
    #pragma unroll
    for (int d = 0; d < 32; d++) acc[d] = 0.f;

    int ntiles = q0 / 64 + 1;
    for (int kt = 0; kt < ntiles; kt++) {
        int ks = kt * 64;
        const float* kbase = Kg + ((size_t)bh * T_LEN + ks) * DH;
        const float* vbase = Vg + ((size_t)bh * T_LEN + ks) * DH;
        for (int li = tid; li < 64 * 16; li += 128) {
            int rr = li >> 4;
            int c4 = (li & 15) * 4;
            *(float4*)&Ks[rr][c4] = *(const float4*)(kbase + rr * DH + c4);
            *(float4*)&Vs[rr][c4] = *(const float4*)(vbase + rr * DH + c4);
        }
        __syncthreads();

        #pragma unroll 1
        for (int sc = 0; sc < 4; sc++) {
            int j0 = sc * 16;
            if (ks + j0 <= r) {
                float s[16];
                float tmax = -1e30f;
                #pragma unroll
                for (int j = 0; j < 16; j++) {
                    const float4* kr4 = (const float4*)&Ks[j0 + j][half * 32];
                    float p = 0.f;
                    #pragma unroll
                    for (int d4 = 0; d4 < 8; d4++) {
                        float4 kv = kr4[d4];
                        p = fmaf(qr[4*d4+0], kv.x, p);
                        p = fmaf(qr[4*d4+1], kv.y, p);
                        p = fmaf(qr[4*d4+2], kv.z, p);
                        p = fmaf(qr[4*d4+3], kv.w, p);
                    }
                    p += __shfl_xor_sync(0xffffffffu, p, 1);
                    p *= 0.125f;
                    if (ks + j0 + j > r) p = -1e30f;
                    s[j] = p;
                    tmax = fmaxf(tmax, p);
                }
                float mnew = fmaxf(mrun, tmax);
                float corr = expf(mrun - mnew);
                lrun *= corr;
                #pragma unroll
                for (int d = 0; d < 32; d++) acc[d] *= corr;
                #pragma unroll
                for (int j = 0; j < 16; j++) {
                    float p = expf(s[j] - mnew);
                    lrun += p;
                    const float4* vr4 = (const float4*)&Vs[j0 + j][half * 32];
                    #pragma unroll
                    for (int d4 = 0; d4 < 8; d4++) {
                        float4 vv = vr4[d4];
                        acc[4*d4+0] = fmaf(p, vv.x, acc[4*d4+0]);
                        acc[4*d4+1] = fmaf(p, vv.y, acc[4*d4+1]);
                        acc[4*d4+2] = fmaf(p, vv.z, acc[4*d4+2]);
                        acc[4*d4+3] = fmaf(p, vv.w, acc[4*d4+3]);
                    }
                }
                mrun = mnew;
            }
        }
        __syncthreads();
    }

    float inv = 1.0f / lrun;
    float* optr = O + ((size_t)(b * T_LEN + r) * C_DIM) + head * DH + half * 32;
    #pragma unroll
    for (int d = 0; d < 32; d++) optr[d] = acc[d] * inv;
}

// ---------------- launch ----------------------------------------------------
extern "C" void kernel_launch(void* const* d_in, const int* in_sizes, int n_in,
                              void* d_out, int out_size) {
    const float* x      = (const float*)d_in[0];
    const float* w_qkv  = (const float*)d_in[1];
    const float* w_proj = (const float*)d_in[2];
    const float* g1     = (const float*)d_in[3];
    const float* g2     = (const float*)d_in[4];
    const float* w1     = (const float*)d_in[5];
    const float* w2     = (const float*)d_in[6];
    const float* w3     = (const float*)d_in[7];
    float* out = (float*)d_out;

    float *p_h, *p_qkv, *p_q, *p_k, *p_v, *p_o, *p_x1, *p_ff;
    cudaGetSymbolAddress((void**)&p_h,   g_h);
    cudaGetSymbolAddress((void**)&p_qkv, g_qkv);
    cudaGetSymbolAddress((void**)&p_q,   g_q);
    cudaGetSymbolAddress((void**)&p_k,   g_k);
    cudaGetSymbolAddress((void**)&p_v,   g_v);
    cudaGetSymbolAddress((void**)&p_o,   g_o);
    cudaGetSymbolAddress((void**)&p_x1,  g_x1);
    cudaGetSymbolAddress((void**)&p_ff,  g_ff);

    rmsnorm_kernel<<<M_TOK, 256>>>(x, g1, p_h);
    tgemm_kernel<0><<<dim3(3 * C_DIM / 128, M_TOK / 128), 256>>>(
        p_h, w_qkv, nullptr, p_qkv, M_TOK, 3 * C_DIM, C_DIM);
    rope_split_kernel<<<(M_TOK * H_NUM * 32) / 256, 256>>>(p_qkv, p_q, p_k, p_v);
    attn_kernel<<<dim3(T_LEN / 64, B_NUM * H_NUM), 128>>>(p_q, p_k, p_v, p_o);
    tgemm_kernel<1><<<dim3(C_DIM / 128, M_TOK / 128), 256>>>(
        p_o, w_proj, x, p_x1, M_TOK, C_DIM, C_DIM);
    rmsnorm_kernel<<<M_TOK, 256>>>(p_x1, g2, p_h);
    tgemm_kernel<0><<<dim3(FF_DIM / 128, M_TOK / 128), 256>>>(
        p_h, w1, nullptr, p_ff, M_TOK, FF_DIM, C_DIM);
    tgemm_kernel<2><<<dim3(FF_DIM / 128, M_TOK / 128), 256>>>(
        p_h, w3, p_ff, p_ff, M_TOK, FF_DIM, C_DIM);
    tgemm_kernel<1><<<dim3(C_DIM / 128, M_TOK / 128), 256>>>(
        p_ff, w2, p_x1, out, M_TOK, C_DIM, FF_DIM);
}

// round 4
// speedup vs baseline: 3.2512x; 1.7289x over previous
#include <cuda_runtime.h>
#include <math.h>
#include <stdint.h>

#define C_DIM   1024
#define H_NUM   16
#define DH      64
#define FF_DIM  4096
#define B_NUM   2
#define T_LEN   2048
#define M_TOK   4096   // B*T

// ---------------- scratch (device globals; no allocation allowed) ----------
__device__ float g_h  [M_TOK * C_DIM];
__device__ float g_qkv[M_TOK * 3 * C_DIM];
__device__ float g_q  [M_TOK * C_DIM];        // [B,H,T,dh]  (pre-scaled, tf32)
__device__ float g_k  [M_TOK * C_DIM];        // [B,H,T,dh]  (tf32)
__device__ float g_v  [M_TOK * C_DIM];        // [B,H,dh,T]  (transposed, tf32)
__device__ float g_o  [M_TOK * C_DIM];        // attention out, [B,T,H*dh]
__device__ float g_x1 [M_TOK * C_DIM];
__device__ float g_ff [M_TOK * FF_DIM];

// ---------------- helpers ----------------------------------------------------
__device__ __forceinline__ uint32_t f2tf32(float x) {
    uint32_t r;
    asm("cvt.rna.tf32.f32 %0, %1;" : "=r"(r) : "f"(x));
    return r;
}
__device__ __forceinline__ float tf32f(float x) { return __uint_as_float(f2tf32(x)); }
__device__ __forceinline__ float4 tf32x4(float4 v) {
    v.x = tf32f(v.x); v.y = tf32f(v.y); v.z = tf32f(v.z); v.w = tf32f(v.w);
    return v;
}
__device__ __forceinline__ void mma_tf32(float c[4],
                                         uint32_t a0, uint32_t a1, uint32_t a2, uint32_t a3,
                                         uint32_t b0, uint32_t b1) {
    asm volatile(
        "mma.sync.aligned.m16n8k8.row.col.f32.tf32.tf32.f32 "
        "{%0,%1,%2,%3}, {%4,%5,%6,%7}, {%8,%9}, {%0,%1,%2,%3};\n"
        : "+f"(c[0]), "+f"(c[1]), "+f"(c[2]), "+f"(c[3])
        : "r"(a0), "r"(a1), "r"(a2), "r"(a3), "r"(b0), "r"(b1));
}
__device__ __forceinline__ void ldsm4(uint32_t& r0, uint32_t& r1,
                                      uint32_t& r2, uint32_t& r3, uint32_t addr) {
    asm volatile("ldmatrix.sync.aligned.m8n8.x4.shared.b16 {%0,%1,%2,%3}, [%4];"
                 : "=r"(r0), "=r"(r1), "=r"(r2), "=r"(r3) : "r"(addr));
}

// ---------------- RMSNorm ----------------------------------------------------
__global__ void rmsnorm_kernel(const float* __restrict__ x,
                               const float* __restrict__ g,
                               float* __restrict__ y) {
    int row = blockIdx.x;
    int tid = threadIdx.x;
    const float4* xr = (const float4*)(x + (size_t)row * C_DIM);
    const float4* gr = (const float4*)g;
    float4*       yr = (float4*)(y + (size_t)row * C_DIM);

    float4 xv = xr[tid];
    float ss = xv.x*xv.x + xv.y*xv.y + xv.z*xv.z + xv.w*xv.w;
    #pragma unroll
    for (int off = 16; off > 0; off >>= 1)
        ss += __shfl_xor_sync(0xffffffffu, ss, off);
    __shared__ float red[8];
    if ((tid & 31) == 0) red[tid >> 5] = ss;
    __syncthreads();
    float tot = 0.f;
    #pragma unroll
    for (int i = 0; i < 8; i++) tot += red[i];
    float inv = rsqrtf(tot * (1.0f / C_DIM) + 1e-5f);

    float4 gv = gr[tid];
    float4 o;
    o.x = xv.x * gv.x * inv;
    o.y = xv.y * gv.y * inv;
    o.z = xv.z * gv.z * inv;
    o.w = xv.w * gv.w * inv;
    yr[tid] = o;
}

// ---------------- tf32 tensor-core GEMM (unchanged from R3) -----------------
template <int MODE>
__global__ __launch_bounds__(256, 2)
void tgemm_kernel(const float* __restrict__ A, const float* __restrict__ W,
                  const float* X, float* Cout, int M, int N, int K) {
    __shared__ float sA[2][2][128 * 8];
    __shared__ float sB[2][2][128 * 8];

    int tid  = threadIdx.x;
    int bm   = blockIdx.y * 128;
    int bn   = blockIdx.x * 128;
    int warp = tid >> 5;
    int lane = tid & 31;
    int wm   = (warp >> 1) * 32;
    int wn   = (warp & 1) * 64;

    int lr = tid >> 1;
    int cc = tid & 1;
    const float* Aptr = A + (size_t)(bm + lr) * K + cc * 4;
    const float* Wptr = W + (size_t)(bn + lr) * K + cc * 4;
    int sstore = lr * 8 + ((cc ^ ((lr >> 2) & 1)) << 2);

    int i   = lane & 7;
    int sub = lane >> 3;
    uint32_t aBase = (uint32_t)__cvta_generic_to_shared(&sA[0][0][0]);
    uint32_t bBase = (uint32_t)__cvta_generic_to_shared(&sB[0][0][0]);
    uint32_t offA[2], offB[4];
    #pragma unroll
    for (int mt = 0; mt < 2; mt++) {
        int row = wm + mt * 16 + (sub & 1) * 8 + i;
        int ch  = (sub >> 1) ^ ((row >> 2) & 1);
        offA[mt] = (uint32_t)(row * 8 + ch * 4) * 4u;
    }
    #pragma unroll
    for (int p = 0; p < 4; p++) {
        int row = wn + p * 16 + (sub >> 1) * 8 + i;
        int ch  = (sub & 1) ^ ((row >> 2) & 1);
        offB[p] = (uint32_t)(row * 8 + ch * 4) * 4u;
    }

    float acc[2][8][4];
    #pragma unroll
    for (int mt = 0; mt < 2; mt++)
        #pragma unroll
        for (int nt = 0; nt < 8; nt++)
            #pragma unroll
            for (int e = 0; e < 4; e++) acc[mt][nt][e] = 0.f;

    {
        float4 a0 = tf32x4(*(const float4*)(Aptr));
        float4 a1 = tf32x4(*(const float4*)(Aptr + 8));
        float4 b0 = tf32x4(*(const float4*)(Wptr));
        float4 b1 = tf32x4(*(const float4*)(Wptr + 8));
        *(float4*)&sA[0][0][sstore] = a0;
        *(float4*)&sA[0][1][sstore] = a1;
        *(float4*)&sB[0][0][sstore] = b0;
        *(float4*)&sB[0][1][sstore] = b1;
    }
    __syncthreads();

    int st = 0;
    for (int k0 = 0; k0 < K; k0 += 16) {
        bool more = (k0 + 16) < K;
        float4 na0, na1, nb0, nb1;
        if (more) {
            na0 = *(const float4*)(Aptr + k0 + 16);
            na1 = *(const float4*)(Aptr + k0 + 24);
            nb0 = *(const float4*)(Wptr + k0 + 16);
            nb1 = *(const float4*)(Wptr + k0 + 24);
        }

        #pragma unroll
        for (int q = 0; q < 2; q++) {
            uint32_t tile = (uint32_t)(st * 2 + q) * (128 * 8 * 4);
            uint32_t aR[2][4], bR[4][4];
            ldsm4(aR[0][0], aR[0][1], aR[0][2], aR[0][3], aBase + tile + offA[0]);
            ldsm4(aR[1][0], aR[1][1], aR[1][2], aR[1][3], aBase + tile + offA[1]);
            #pragma unroll
            for (int p = 0; p < 4; p++)
                ldsm4(bR[p][0], bR[p][1], bR[p][2], bR[p][3], bBase + tile + offB[p]);
            #pragma unroll
            for (int mt = 0; mt < 2; mt++)
                #pragma unroll
                for (int nt = 0; nt < 8; nt++) {
                    int p  = nt >> 1;
                    int e0 = (nt & 1) * 2;
                    mma_tf32(acc[mt][nt],
                             aR[mt][0], aR[mt][1], aR[mt][2], aR[mt][3],
                             bR[p][e0], bR[p][e0 + 1]);
                }
        }

        if (more) {
            *(float4*)&sA[st ^ 1][0][sstore] = tf32x4(na0);
            *(float4*)&sA[st ^ 1][1][sstore] = tf32x4(na1);
            *(float4*)&sB[st ^ 1][0][sstore] = tf32x4(nb0);
            *(float4*)&sB[st ^ 1][1][sstore] = tf32x4(nb1);
        }
        __syncthreads();
        st ^= 1;
    }

    int g = lane >> 2;
    int t = lane & 3;
    #pragma unroll
    for (int mt = 0; mt < 2; mt++) {
        #pragma unroll
        for (int half = 0; half < 2; half++) {
            int row = bm + wm + mt * 16 + half * 8 + g;
            float*       crow = Cout + (size_t)row * N;
            const float* xrow = (MODE != 0) ? (X + (size_t)row * N) : nullptr;
            #pragma unroll
            for (int nt = 0; nt < 8; nt++) {
                int col = bn + wn + nt * 8 + 2 * t;
                float2 v;
                v.x = acc[mt][nt][half * 2 + 0];
                v.y = acc[mt][nt][half * 2 + 1];
                if (MODE == 1) {
                    float2 xv = *(const float2*)(xrow + col);
                    v.x += xv.x; v.y += xv.y;
                }
                if (MODE == 2) {
                    float2 xv = *(const float2*)(xrow + col);
                    v.x *= xv.x / (1.f + expf(-xv.x));
                    v.y *= xv.y / (1.f + expf(-xv.y));
                }
                *(float2*)(crow + col) = v;
            }
        }
    }
}

// ---------------- RoPE + split qkv -> q,k in [B,H,T,dh] (tf32, q pre-scaled)
#define Q_SCALE (0.125f * 1.44269504088896f)   // 1/sqrt(64) * log2(e)
__global__ void rope_split_kernel(const float* __restrict__ qkv,
                                  float* __restrict__ q,
                                  float* __restrict__ k) {
    int idx = blockIdx.x * blockDim.x + threadIdx.x;
    int i = idx & 31;
    int h = (idx >> 5) & 15;
    int m = idx >> 9;
    int b = m >> 11;
    int t = m & 2047;

    const float* base = qkv + (size_t)m * (3 * C_DIM) + h * DH + 2 * i;
    float q1 = base[0],     q2 = base[1];
    float k1 = base[C_DIM], k2 = base[C_DIM + 1];

    float freq = expf(-(2.0f * (float)i) * (1.0f / 64.0f) * 9.210340371976184f);
    float th = (float)t * freq;
    float s, c;
    sincosf(th, &s, &c);

    size_t o = ((size_t)(b * H_NUM + h) * T_LEN + t) * DH + 2 * i;
    q[o]   = tf32f((q1 * c - q2 * s) * Q_SCALE);
    q[o+1] = tf32f((q1 * s + q2 * c) * Q_SCALE);
    k[o]   = tf32f(k1 * c - k2 * s);
    k[o+1] = tf32f(k1 * s + k2 * c);
}

// ---------------- V transpose: qkv v-section -> [B,H,dh,T], tf32 ------------
__global__ void vtrans_kernel(const float* __restrict__ qkv,
                              float* __restrict__ vt) {
    __shared__ float s[64][65];
    int bh = blockIdx.y;
    int b  = bh >> 4;
    int h  = bh & 15;
    int t0 = blockIdx.x * 64;
    int tid = threadIdx.x;

    for (int idx = tid; idx < 64 * 64; idx += 256) {
        int tok = idx >> 6, d = idx & 63;
        s[tok][d] = qkv[(size_t)(b * T_LEN + t0 + tok) * (3 * C_DIM)
                        + 2 * C_DIM + h * DH + d];
    }
    __syncthreads();
    for (int idx = tid; idx < 64 * 64; idx += 256) {
        int d = idx >> 6, tok = idx & 63;
        vt[((size_t)bh * DH + d) * T_LEN + t0 + tok] = tf32f(s[tok][d]);
    }
}

// ---------------- tensor-core causal flash attention ------------------------
// grid (T/64, B*H), 128 threads (4 warps x 16 query rows).
// smem: sQ[64][68] (reused as P), sK[64][68], sV[64][68] (Vt tile: dh x keys)
#define APAD 68
__global__ __launch_bounds__(128)
void attn_mma_kernel(const float* __restrict__ Q,
                     const float* __restrict__ Kg,
                     const float* __restrict__ Vt,
                     float* __restrict__ O) {
    extern __shared__ float sm[];
    float* sQ = sm;                    // 64*APAD floats (later: P)
    float* sK = sm + 64 * APAD;
    float* sV = sm + 2 * 64 * APAD;

    int bh   = blockIdx.y;
    int b    = bh >> 4;
    int head = bh & 15;
    int q0   = blockIdx.x * 64;
    int tid  = threadIdx.x;
    int warp = tid >> 5;
    int lane = tid & 31;
    int wm   = warp * 16;
    int g    = lane >> 2;
    int t    = lane & 3;
    int i    = lane & 7;
    int sub  = lane >> 3;

    uint32_t smBase = (uint32_t)__cvta_generic_to_shared(sm);
    const uint32_t K_OFF = 64 * APAD * 4;
    const uint32_t V_OFF = 2 * 64 * APAD * 4;

    // load Q tile
    const float* qg = Q + ((size_t)bh * T_LEN + q0) * DH;
    for (int idx = tid; idx < 64 * 16; idx += 128) {
        int r = idx >> 4, c4 = (idx & 15) * 4;
        *(float4*)&sQ[r * APAD + c4] = *(const float4*)(qg + r * DH + c4);
    }
    __syncthreads();

    // Q fragments (held in registers for all key tiles)
    uint32_t qf[8][4];
    {
        int row = wm + (sub & 1) * 8 + i;
        #pragma unroll
        for (int kq = 0; kq < 8; kq++) {
            uint32_t off = (uint32_t)(row * APAD + kq * 8 + (sub >> 1) * 4) * 4u;
            ldsm4(qf[kq][0], qf[kq][1], qf[kq][2], qf[kq][3], smBase + off);
        }
    }

    float accO[8][4];
    #pragma unroll
    for (int nt = 0; nt < 8; nt++)
        #pragma unroll
        for (int e = 0; e < 4; e++) accO[nt][e] = 0.f;
    float m0 = -1e30f, m1 = -1e30f, l0 = 0.f, l1 = 0.f;

    int r0 = q0 + wm + g;
    int r1 = r0 + 8;
    int prow0 = (wm + g) * APAD;
    int prow1 = (wm + g + 8) * APAD;
    int arow  = wm + (sub & 1) * 8 + i;          // P a-frag row

    int ntiles = q0 / 64 + 1;
    for (int kt = 0; kt < ntiles; kt++) {
        int ks = kt * 64;
        const float* kbase = Kg + ((size_t)bh * T_LEN + ks) * DH;
        const float* vbase = Vt + (size_t)bh * DH * T_LEN + ks;
        for (int idx = tid; idx < 64 * 16; idx += 128) {
            int r = idx >> 4, c4 = (idx & 15) * 4;
            *(float4*)&sK[r * APAD + c4] = *(const float4*)(kbase + r * DH + c4);
            *(float4*)&sV[r * APAD + c4] = *(const float4*)(vbase + (size_t)r * T_LEN + c4);
        }
        __syncthreads();

        if (ks <= q0 + wm + 15) {                 // warp has unmasked rows
            // ---- S = Q @ K^T ----
            float s[8][4];
            #pragma unroll
            for (int nt = 0; nt < 8; nt++)
                #pragma unroll
                for (int e = 0; e < 4; e++) s[nt][e] = 0.f;

            #pragma unroll
            for (int kq = 0; kq < 8; kq++) {
                uint32_t bR[4][4];
                #pragma unroll
                for (int p = 0; p < 4; p++) {
                    int row = p * 16 + (sub >> 1) * 8 + i;
                    uint32_t off = K_OFF +
                        (uint32_t)(row * APAD + kq * 8 + (sub & 1) * 4) * 4u;
                    ldsm4(bR[p][0], bR[p][1], bR[p][2], bR[p][3], smBase + off);
                }
                #pragma unroll
                for (int nt = 0; nt < 8; nt++)
                    mma_tf32(s[nt], qf[kq][0], qf[kq][1], qf[kq][2], qf[kq][3],
                             bR[nt >> 1][(nt & 1) * 2], bR[nt >> 1][(nt & 1) * 2 + 1]);
            }

            // ---- causal mask ----
            if (ks + 63 > q0 + wm) {              // partially masked tile
                #pragma unroll
                for (int nt = 0; nt < 8; nt++) {
                    int kc = ks + nt * 8 + 2 * t;
                    if (kc     > r0) s[nt][0] = -1e30f;
                    if (kc + 1 > r0) s[nt][1] = -1e30f;
                    if (kc     > r1) s[nt][2] = -1e30f;
                    if (kc + 1 > r1) s[nt][3] = -1e30f;
                }
            }

            // ---- online softmax (log2 domain; Q pre-scaled) ----
            float tm0 = -1e30f, tm1 = -1e30f;
            #pragma unroll
            for (int nt = 0; nt < 8; nt++) {
                tm0 = fmaxf(tm0, fmaxf(s[nt][0], s[nt][1]));
                tm1 = fmaxf(tm1, fmaxf(s[nt][2], s[nt][3]));
            }
            tm0 = fmaxf(tm0, __shfl_xor_sync(0xffffffffu, tm0, 1));
            tm0 = fmaxf(tm0, __shfl_xor_sync(0xffffffffu, tm0, 2));
            tm1 = fmaxf(tm1, __shfl_xor_sync(0xffffffffu, tm1, 1));
            tm1 = fmaxf(tm1, __shfl_xor_sync(0xffffffffu, tm1, 2));

            float mn0 = fmaxf(m0, tm0), mn1 = fmaxf(m1, tm1);
            float c0 = exp2f(m0 - mn0), c1 = exp2f(m1 - mn1);

            float ps0 = 0.f, ps1 = 0.f;
            #pragma unroll
            for (int nt = 0; nt < 8; nt++) {
                float2 pa, pb;
                pa.x = exp2f(s[nt][0] - mn0); pa.y = exp2f(s[nt][1] - mn0);
                pb.x = exp2f(s[nt][2] - mn1); pb.y = exp2f(s[nt][3] - mn1);
                ps0 += pa.x + pa.y; ps1 += pb.x + pb.y;
                pa.x = tf32f(pa.x); pa.y = tf32f(pa.y);
                pb.x = tf32f(pb.x); pb.y = tf32f(pb.y);
                int col = nt * 8 + 2 * t;
                *(float2*)&sQ[prow0 + col] = pa;
                *(float2*)&sQ[prow1 + col] = pb;
            }
            ps0 += __shfl_xor_sync(0xffffffffu, ps0, 1);
            ps0 += __shfl_xor_sync(0xffffffffu, ps0, 2);
            ps1 += __shfl_xor_sync(0xffffffffu, ps1, 1);
            ps1 += __shfl_xor_sync(0xffffffffu, ps1, 2);

            l0 = l0 * c0 + ps0;
            l1 = l1 * c1 + ps1;
            m0 = mn0; m1 = mn1;

            #pragma unroll
            for (int nt = 0; nt < 8; nt++) {
                accO[nt][0] *= c0; accO[nt][1] *= c0;
                accO[nt][2] *= c1; accO[nt][3] *= c1;
            }
            __syncwarp();

            // ---- O += P @ V  (P rows = this warp's own rows) ----
            #pragma unroll
            for (int kp = 0; kp < 8; kp++) {
                uint32_t aP[4];
                ldsm4(aP[0], aP[1], aP[2], aP[3],
                      smBase + (uint32_t)(arow * APAD + kp * 8 + (sub >> 1) * 4) * 4u);
                uint32_t bV[4][4];
                #pragma unroll
                for (int p = 0; p < 4; p++) {
                    int row = p * 16 + (sub >> 1) * 8 + i;
                    uint32_t off = V_OFF +
                        (uint32_t)(row * APAD + kp * 8 + (sub & 1) * 4) * 4u;
                    ldsm4(bV[p][0], bV[p][1], bV[p][2], bV[p][3], smBase + off);
                }
                #pragma unroll
                for (int nt = 0; nt < 8; nt++)
                    mma_tf32(accO[nt], aP[0], aP[1], aP[2], aP[3],
                             bV[nt >> 1][(nt & 1) * 2], bV[nt >> 1][(nt & 1) * 2 + 1]);
            }
        }
        __syncthreads();
    }

    // ---- epilogue ----
    float inv0 = 1.f / l0, inv1 = 1.f / l1;
    float* o0 = O + ((size_t)(b * T_LEN + r0)) * C_DIM + head * DH;
    float* o1 = O + ((size_t)(b * T_LEN + r1)) * C_DIM + head * DH;
    #pragma unroll
    for (int nt = 0; nt < 8; nt++) {
        int col = nt * 8 + 2 * t;
        float2 v0, v1;
        v0.x = accO[nt][0] * inv0; v0.y = accO[nt][1] * inv0;
        v1.x = accO[nt][2] * inv1; v1.y = accO[nt][3] * inv1;
        *(float2*)(o0 + col) = v0;
        *(float2*)(o1 + col) = v1;
    }
}

// ---------------- launch ----------------------------------------------------
extern "C" void kernel_launch(void* const* d_in, const int* in_sizes, int n_in,
                              void* d_out, int out_size) {
    const float* x      = (const float*)d_in[0];
    const float* w_qkv  = (const float*)d_in[1];
    const float* w_proj = (const float*)d_in[2];
    const float* g1     = (const float*)d_in[3];
    const float* g2     = (const float*)d_in[4];
    const float* w1     = (const float*)d_in[5];
    const float* w2     = (const float*)d_in[6];
    const float* w3     = (const float*)d_in[7];
    float* out = (float*)d_out;

    float *p_h, *p_qkv, *p_q, *p_k, *p_v, *p_o, *p_x1, *p_ff;
    cudaGetSymbolAddress((void**)&p_h,   g_h);
    cudaGetSymbolAddress((void**)&p_qkv, g_qkv);
    cudaGetSymbolAddress((void**)&p_q,   g_q);
    cudaGetSymbolAddress((void**)&p_k,   g_k);
    cudaGetSymbolAddress((void**)&p_v,   g_v);
    cudaGetSymbolAddress((void**)&p_o,   g_o);
    cudaGetSymbolAddress((void**)&p_x1,  g_x1);
    cudaGetSymbolAddress((void**)&p_ff,  g_ff);

    int attn_smem = 3 * 64 * APAD * 4;   // 52,224 B
    cudaFuncSetAttribute(attn_mma_kernel,
                         cudaFuncAttributeMaxDynamicSharedMemorySize, attn_smem);

    rmsnorm_kernel<<<M_TOK, 256>>>(x, g1, p_h);
    tgemm_kernel<0><<<dim3(3 * C_DIM / 128, M_TOK / 128), 256>>>(
        p_h, w_qkv, nullptr, p_qkv, M_TOK, 3 * C_DIM, C_DIM);
    rope_split_kernel<<<(M_TOK * H_NUM * 32) / 256, 256>>>(p_qkv, p_q, p_k);
    vtrans_kernel<<<dim3(T_LEN / 64, B_NUM * H_NUM), 256>>>(p_qkv, p_v);
    attn_mma_kernel<<<dim3(T_LEN / 64, B_NUM * H_NUM), 128, attn_smem>>>(
        p_q, p_k, p_v, p_o);
    tgemm_kernel<1><<<dim3(C_DIM / 128, M_TOK / 128), 256>>>(
        p_o, w_proj, x, p_x1, M_TOK, C_DIM, C_DIM);
    rmsnorm_kernel<<<M_TOK, 256>>>(p_x1, g2, p_h);
    tgemm_kernel<0><<<dim3(FF_DIM / 128, M_TOK / 128), 256>>>(
        p_h, w1, nullptr, p_ff, M_TOK, FF_DIM, C_DIM);
    tgemm_kernel<2><<<dim3(FF_DIM / 128, M_TOK / 128), 256>>>(
        p_h, w3, p_ff, p_ff, M_TOK, FF_DIM, C_DIM);
    tgemm_kernel<1><<<dim3(C_DIM / 128, M_TOK / 128), 256>>>(
        p_ff, w2, p_x1, out, M_TOK, C_DIM, FF_DIM);
}